// round 3
// baseline (speedup 1.0000x reference)
#include <cuda_runtime.h>
#include <math.h>

// x: [64, 3, 512, 512] fp32. Per 8x8 block compute |FFT2| at bins
// (0,1),(1,0),(1,1),(2,2),(3,3),(4,4), mean over the 64x64 block grid,
// output [64, 18] = [plane(192), band(6)].
//
// Separable DFT: F(u,v) = sum_m W_u[m] * R_v(m), R_v(m) = row-DFT of row m at freq v.
// Pure HBM-bound: 201MB read once, coalesced float4 loads.

#define PLANE_ELEMS (512 * 512)
#define NBLOCKS_PER_PLANE 4096   // 64 x 64 blocks of 8x8
#define THREADS 512

__global__ __launch_bounds__(THREADS, 2)
void dct_bands_kernel(const float* __restrict__ x, float* __restrict__ out) {
    const int plane = blockIdx.x;                       // b*3 + c, 0..191
    const float* __restrict__ base = x + (size_t)plane * PLANE_ELEMS;
    const int tid = threadIdx.x;

    constexpr float S = 0.70710678118654752440f;
    // Twiddle tables: e^{-i * m * theta}, theta = 45/90/135 degrees.
    // Fully-unrolled loop -> constant indices -> ptxas folds these to immediates.
    const float C45[8]  = {1.f,  S, 0.f, -S, -1.f, -S, 0.f,  S};
    const float S45[8]  = {0.f,  S, 1.f,  S,  0.f, -S, -1.f, -S};
    const float C90[8]  = {1.f, 0.f, -1.f, 0.f, 1.f, 0.f, -1.f, 0.f};
    const float S90[8]  = {0.f, 1.f, 0.f, -1.f, 0.f, 1.f, 0.f, -1.f};
    const float C135[8] = {1.f, -S, 0.f,  S, -1.f,  S, 0.f, -S};
    const float S135[8] = {0.f,  S, -1.f, S,  0.f, -S, 1.f, -S};

    float sum0 = 0.f, sum1 = 0.f, sum2 = 0.f, sum3 = 0.f, sum4 = 0.f, sum5 = 0.f;

    #pragma unroll 1
    for (int k = 0; k < NBLOCKS_PER_PLANE / THREADS; ++k) {
        const int bl = tid + (k << 9);            // block index within plane
        const int gi = bl >> 6;                   // block row (0..63)
        const int gj = bl & 63;                   // block col (0..63)
        const float* bp = base + ((size_t)(gi << 3) << 9) + (gj << 3);

        // Accumulators: 5 complex bins + 1 real bin
        float a01r = 0.f, a01i = 0.f;  // (u=0, v=1)
        float a10r = 0.f, a10i = 0.f;  // (u=1, v=0)
        float a11r = 0.f, a11i = 0.f;  // (u=1, v=1)
        float a22r = 0.f, a22i = 0.f;  // (u=2, v=2)
        float a33r = 0.f, a33i = 0.f;  // (u=3, v=3)
        float a44  = 0.f;              // (u=4, v=4) purely real

        #pragma unroll
        for (int m = 0; m < 8; ++m) {
            const float4 lo = *reinterpret_cast<const float4*>(bp + m * 512);
            const float4 hi = *reinterpret_cast<const float4*>(bp + m * 512 + 4);
            const float x0 = lo.x, x1 = lo.y, x2 = lo.z, x3 = lo.w;
            const float x4 = hi.x, x5 = hi.y, x6 = hi.z, x7 = hi.w;

            // Shared butterflies
            const float p  = x1 - x3 - x5 + x7;
            const float q  = x1 + x3 - x5 - x7;
            const float e0 = x0 - x4;       // even diff
            const float e2 = x2 - x6;

            // Row DFT at v = 0,1,2,3,4 (sign convention e^{-i...}; |.| is sign-agnostic)
            const float r0  = x0 + x1 + x2 + x3 + x4 + x5 + x6 + x7;
            const float re1 = e0 + p * S;
            const float im1 = -(q * S + e2);
            const float re2 = x0 - x2 + x4 - x6;
            const float im2 = -(x1 - x3 + x5 - x7);
            const float re3 = e0 - p * S;
            const float im3 = -(q * S - e2);
            const float r4  = x0 - x1 + x2 - x3 + x4 - x5 + x6 - x7;

            // Column twiddles for this m: W_u[m] = (cos, -sin)
            const float w1r = C45[m],  w1i = -S45[m];
            const float w2r = C90[m],  w2i = -S90[m];
            const float w3r = C135[m], w3i = -S135[m];

            // (0,1): plain sum of c1
            a01r += re1;                  a01i += im1;
            // (1,0): real r0 * W1
            a10r += r0 * w1r;             a10i += r0 * w1i;
            // (1,1): c1 * W1
            a11r += re1 * w1r - im1 * w1i;
            a11i += re1 * w1i + im1 * w1r;
            // (2,2): c2 * W2
            a22r += re2 * w2r - im2 * w2i;
            a22i += re2 * w2i + im2 * w2r;
            // (3,3): c3 * W3
            a33r += re3 * w3r - im3 * w3i;
            a33i += re3 * w3i + im3 * w3r;
            // (4,4): r4 * (-1)^m
            a44 += (m & 1) ? -r4 : r4;
        }

        sum0 += sqrtf(a01r * a01r + a01i * a01i);
        sum1 += sqrtf(a10r * a10r + a10i * a10i);
        sum2 += sqrtf(a11r * a11r + a11i * a11i);
        sum3 += sqrtf(a22r * a22r + a22i * a22i);
        sum4 += sqrtf(a33r * a33r + a33i * a33i);
        sum5 += fabsf(a44);
    }

    // ---- CTA reduction: 512 threads x 6 floats -> out[plane*6 + band] ----
    float v[6] = {sum0, sum1, sum2, sum3, sum4, sum5};

    #pragma unroll
    for (int j = 0; j < 6; ++j) {
        #pragma unroll
        for (int o = 16; o > 0; o >>= 1)
            v[j] += __shfl_down_sync(0xffffffffu, v[j], o);
    }

    __shared__ float red[16][6];
    const int lane = tid & 31, warp = tid >> 5;
    if (lane == 0) {
        #pragma unroll
        for (int j = 0; j < 6; ++j) red[warp][j] = v[j];
    }
    __syncthreads();

    if (tid < 6) {
        float t = 0.f;
        #pragma unroll
        for (int w = 0; w < 16; ++w) t += red[w][tid];
        out[plane * 6 + tid] = t * (1.0f / (float)NBLOCKS_PER_PLANE);
    }
}

extern "C" void kernel_launch(void* const* d_in, const int* in_sizes, int n_in,
                              void* d_out, int out_size) {
    const float* x = (const float*)d_in[0];
    float* out = (float*)d_out;
    const int n_planes = in_sizes[0] / PLANE_ELEMS;   // 64*3 = 192
    dct_bands_kernel<<<n_planes, THREADS>>>(x, out);
}